// round 4
// baseline (speedup 1.0000x reference)
#include <cuda_runtime.h>
#include <cstdint>

// out[2048,122880] = tile(x1[2048,4096] @ x2[4096,4096], 30x), fp32, TF32 mma.sync.
// R4: persistent 4-tile CTAs; previous tile's 30-rep streaming stores are sliced
// into the current tile's mainloop (smem C-buffer), hiding store-DRAM time under
// tensor time. Fragment-order prepass unchanged from R3.
#define MDIM 2048
#define NDIM 4096
#define KDIM 4096
#define NREP 30
#define OUTN (NDIM * NREP)

#define BM 128
#define BN 128
#define BK 32
#define NKT (KDIM / BK)          // 128
#define STAGES 4
#define STAGE_BYTES 32768        // 16KB A frags + 16KB B frags
#define CB_OFF (STAGES * STAGE_BYTES)        // 131072
#define CB_STRIDE 132            // floats per C-buffer row
#define SMEM_TOTAL (CB_OFF + 128 * CB_STRIDE * 4)   // 198656

__device__ float g_Af[(size_t)MDIM * KDIM];
__device__ float g_Bf[(size_t)NDIM * KDIM];

__device__ __forceinline__ uint32_t f2tf32(float x) {
    uint32_t y;
    asm("cvt.rna.tf32.f32 %0, %1;" : "=r"(y) : "f"(x));
    return y;
}
__device__ __forceinline__ float rtf(float x) { return __uint_as_float(f2tf32(x)); }

__device__ __forceinline__ uint32_t smem_u32(const void* p) {
    uint32_t a;
    asm("{ .reg .u64 t; cvta.to.shared.u64 t, %1; cvt.u32.u64 %0, t; }" : "=r"(a) : "l"(p));
    return a;
}
__device__ __forceinline__ void cp_async16(uint32_t dst, const void* src) {
    asm volatile("cp.async.cg.shared.global [%0], [%1], 16;" :: "r"(dst), "l"(src) : "memory");
}
#define CP_COMMIT() asm volatile("cp.async.commit_group;" ::: "memory")
#define CP_WAIT2()  asm volatile("cp.async.wait_group 2;" ::: "memory")
#define CP_WAIT0()  asm volatile("cp.async.wait_group 0;" ::: "memory")

__device__ __forceinline__ void mma_tf32(float c[4], uint32_t a0, uint32_t a1,
                                         uint32_t a2, uint32_t a3,
                                         uint32_t b0, uint32_t b1) {
    asm volatile(
        "mma.sync.aligned.m16n8k8.row.col.f32.tf32.tf32.f32 "
        "{%0,%1,%2,%3},{%4,%5,%6,%7},{%8,%9},{%0,%1,%2,%3};"
        : "+f"(c[0]), "+f"(c[1]), "+f"(c[2]), "+f"(c[3])
        : "r"(a0), "r"(a1), "r"(a2), "r"(a3), "r"(b0), "r"(b1));
}

// ---------------- prepass A: [M][K] -> fragment order, tf32-rounded ----------------
__global__ __launch_bounds__(256)
void prepA_kernel(const float* __restrict__ A) {
    __shared__ float sA[16][516];
    const int bx = blockIdx.x, m16 = blockIdx.y;
    const int tid = threadIdx.x, lane = tid & 31, warp = tid >> 5;
    #pragma unroll
    for (int i = 0; i < 8; i++) {
        const int idx = i * 256 + tid;
        const int r = idx >> 7, c4 = idx & 127;
        float4 v = *(const float4*)&A[(size_t)(m16 * 16 + r) * KDIM + bx * 512 + c4 * 4];
        v.x = rtf(v.x); v.y = rtf(v.y); v.z = rtf(v.z); v.w = rtf(v.w);
        *(float4*)&sA[r][c4 * 4] = v;
    }
    __syncthreads();
    const int r = lane >> 2, cq = lane & 3;
    #pragma unroll
    for (int t = 0; t < 8; t++) {
        const int k8l = warp * 8 + t;
        float4 w;
        w.x = sA[r][k8l * 8 + cq];
        w.y = sA[r + 8][k8l * 8 + cq];
        w.z = sA[r][k8l * 8 + cq + 4];
        w.w = sA[r + 8][k8l * 8 + cq + 4];
        const size_t o = ((size_t)m16 * 512 + bx * 64 + k8l) * 32 + lane;
        ((float4*)g_Af)[o] = w;
    }
}

// ---------------- prepass B: [K][N] -> fragment order ----------------
__global__ __launch_bounds__(256)
void prepB_kernel(const float* __restrict__ B) {
    __shared__ float sB[128][68];
    const int bx = blockIdx.x, by = blockIdx.y;
    const int tid = threadIdx.x, lane = tid & 31, warp = tid >> 5;
    #pragma unroll
    for (int i = 0; i < 8; i++) {
        const int idx = i * 256 + tid;
        const int kr = idx >> 4, c4 = idx & 15;
        float4 v = *(const float4*)&B[(size_t)(bx * 128 + kr) * NDIM + by * 64 + c4 * 4];
        v.x = rtf(v.x); v.y = rtf(v.y); v.z = rtf(v.z); v.w = rtf(v.w);
        *(float4*)&sB[kr][c4 * 4] = v;
    }
    __syncthreads();
    const int r = lane >> 2, cq = lane & 3;
    #pragma unroll
    for (int t = 0; t < 8; t++) {
        const int id = warp * 8 + t;
        const int n16l = id >> 4, k8l = id & 15;
        float4 w;
        w.x = sB[k8l * 8 + cq][n16l * 16 + r];
        w.y = sB[k8l * 8 + cq + 4][n16l * 16 + r];
        w.z = sB[k8l * 8 + cq][n16l * 16 + 8 + r];
        w.w = sB[k8l * 8 + cq + 4][n16l * 16 + 8 + r];
        const size_t o = ((size_t)(by * 4 + n16l) * 512 + bx * 16 + k8l) * 32 + lane;
        ((float4*)g_Bf)[o] = w;
    }
}

// ---------------- persistent GEMM: 128 CTAs x 4 tiles, store/compute interleave --------
__global__ __launch_bounds__(256, 1)
void Model_82454782148931_gemm(float* __restrict__ out) {
    extern __shared__ char smem[];
    const uint32_t sbase = smem_u32(smem);
    float* CB = (float*)(smem + CB_OFF);

    const int tid  = threadIdx.x;
    const int lane = tid & 31;
    const int warp = tid >> 5;
    const int wm   = warp & 1;              // 0..1 -> 64-row slab
    const int wn   = warp >> 1;             // 0..3 -> 32-col slab
    const int mi   = blockIdx.x & 15;       // 16 m-tiles
    const int ngrp = blockIdx.x >> 4;       // 8 n-groups
    const int bm16 = mi * 8;
    const int bm0  = mi * BM;

    const float4* Af4 = (const float4*)g_Af;
    const float4* Bf4 = (const float4*)g_Bf;

    float c[4][4][4];
    #pragma unroll
    for (int mt = 0; mt < 4; mt++)
        #pragma unroll
        for (int nt = 0; nt < 4; nt++)
            #pragma unroll
            for (int i = 0; i < 4; i++) c[mt][nt][i] = 0.0f;

    int prev_bn0 = 0;

    #pragma unroll 1
    for (int t = 0; t < 4; t++) {
        const int ni   = ngrp + 8 * t;      // concurrent CTAs cluster in one 8-col slab
        const int bn16 = ni * 8;
        const int bn0  = ni * BN;

        auto load_stage = [&](int s, int kt) {
            const uint32_t ab = sbase + s * STAGE_BYTES;
            #pragma unroll
            for (int i = 0; i < 4; i++) {
                const int idx = i * 256 + tid;    // 1024 float4 per operand
                const int m16l = idx >> 7;
                const int k8l  = (idx >> 5) & 3;
                const int ln   = idx & 31;
                cp_async16(ab + idx * 16,
                           Af4 + ((size_t)(bm16 + m16l) * 512 + kt * 4 + k8l) * 32 + ln);
                cp_async16(ab + 16384 + idx * 16,
                           Bf4 + ((size_t)(bn16 + m16l) * 512 + kt * 4 + k8l) * 32 + ln);
            }
        };

        load_stage(0, 0); CP_COMMIT();
        load_stage(1, 1); CP_COMMIT();
        load_stage(2, 2); CP_COMMIT();

        #pragma unroll 1
        for (int kt = 0; kt < NKT; kt++) {
            const int s = kt & 3;
            CP_WAIT2();                     // stage kt landed; kt+1,kt+2 in flight
            __syncthreads();
            if (kt + 3 < NKT) load_stage((kt + 3) & 3, kt + 3);
            CP_COMMIT();

            const char* ap = smem + s * STAGE_BYTES + (size_t)(wm * 4) * 4 * 512 + lane * 16;
            const char* bp = smem + s * STAGE_BYTES + 16384 + (size_t)(wn * 2) * 4 * 512 + lane * 16;
            #pragma unroll
            for (int ks = 0; ks < 4; ks++) {
                uint4 af[4], bf[2];
                #pragma unroll
                for (int mt = 0; mt < 4; mt++)
                    af[mt] = *(const uint4*)(ap + (mt * 4 + ks) * 512);
                #pragma unroll
                for (int j = 0; j < 2; j++)
                    bf[j] = *(const uint4*)(bp + (j * 4 + ks) * 512);
                #pragma unroll
                for (int mt = 0; mt < 4; mt++)
                    #pragma unroll
                    for (int j = 0; j < 2; j++) {
                        mma_tf32(c[mt][2 * j],     af[mt].x, af[mt].y, af[mt].z, af[mt].w,
                                 bf[j].x, bf[j].y);
                        mma_tf32(c[mt][2 * j + 1], af[mt].x, af[mt].y, af[mt].z, af[mt].w,
                                 bf[j].z, bf[j].w);
                    }
            }

            // one store-slice of the previous tile: rep (s'>>2), col-block (s'&3)
            if (t > 0 && kt >= 8) {
                const int sp  = kt - 8;           // 0..119
                const int cb  = sp & 3;           // 32-col block
                const int rep = sp >> 2;          // 0..29
                float* orep = out + (size_t)rep * NDIM + prev_bn0 + cb * 32;
                #pragma unroll
                for (int i = 0; i < 4; i++) {
                    const int idx = i * 256 + tid;     // 1024 float4
                    const int f4  = idx & 7;
                    const int row = idx >> 3;
                    const float4 v = *(const float4*)&CB[row * CB_STRIDE + cb * 32 + f4 * 4];
                    __stcs((float4*)(orep + (size_t)(bm0 + row) * OUTN + f4 * 4), v);
                }
            }
        }

        CP_WAIT0();
        __syncthreads();     // slices of prev tile done; stages drained

        if (t < 3) {
            // park accumulators in C-buffer; reset
            #pragma unroll
            for (int mt = 0; mt < 4; mt++) {
                const int row0 = wm * 64 + mt * 16 + (lane >> 2);
                #pragma unroll
                for (int nt = 0; nt < 4; nt++) {
                    const int col = wn * 32 + nt * 8 + (lane & 3) * 2;
                    *(float2*)&CB[row0 * CB_STRIDE + col] =
                        make_float2(c[mt][nt][0], c[mt][nt][1]);
                    *(float2*)&CB[(row0 + 8) * CB_STRIDE + col] =
                        make_float2(c[mt][nt][2], c[mt][nt][3]);
                    #pragma unroll
                    for (int i = 0; i < 4; i++) c[mt][nt][i] = 0.0f;
                }
            }
            prev_bn0 = bn0;
            __syncthreads();   // CB visible before next tile's slices
        } else {
            // last tile: stream all 30 reps straight from registers
            #pragma unroll
            for (int mt = 0; mt < 4; mt++) {
                const int row0 = bm0 + wm * 64 + mt * 16 + (lane >> 2);
                #pragma unroll
                for (int nt = 0; nt < 4; nt++) {
                    const int col = bn0 + wn * 32 + nt * 8 + (lane & 3) * 2;
                    const float2 v01 = make_float2(c[mt][nt][0], c[mt][nt][1]);
                    const float2 v23 = make_float2(c[mt][nt][2], c[mt][nt][3]);
                    float* p0 = out + (size_t)row0 * OUTN + col;
                    float* p1 = p0 + (size_t)8 * OUTN;
                    #pragma unroll
                    for (int rep = 0; rep < NREP; rep++) {
                        __stcs((float2*)(p0 + (size_t)rep * NDIM), v01);
                        __stcs((float2*)(p1 + (size_t)rep * NDIM), v23);
                    }
                }
            }
        }
    }
}

extern "C" void kernel_launch(void* const* d_in, const int* in_sizes, int n_in,
                              void* d_out, int out_size) {
    const float* x1 = (const float*)d_in[0];
    const float* x2 = (const float*)d_in[1];
    float* out = (float*)d_out;

    prepA_kernel<<<dim3(KDIM / 512, MDIM / 16), 256>>>(x1);
    prepB_kernel<<<dim3(KDIM / 128, NDIM / 64), 256>>>(x2);

    cudaFuncSetAttribute(Model_82454782148931_gemm,
                         cudaFuncAttributeMaxDynamicSharedMemorySize, SMEM_TOTAL);
    Model_82454782148931_gemm<<<128, 256, SMEM_TOTAL>>>(out);
}